// round 13
// baseline (speedup 1.0000x reference)
#include <cuda_runtime.h>

// out[b,i] = g[b, i>>7] * (W[i,:] . x[b,:]) + bias[i]
// g = sigmoid(x @ gate_w + gate_b), 8 smallest gates per row zeroed.
//
// R8 design, third submission (R9/R10 were broker infra failures, no data):
// 512 GEMM blocks = 8 row-tiles x 16 k-tiles x 4 batch-quarters.
//  - per thread: 2 rows x 8 batches, acc = 32 regs, ~90 regs total
//  - 4 blocks/SM -> 4 warps/SMSP (2x latency hiding vs R6)
//  - batch-quarter quads (adjacent blockIdx) share W tiles via L2
//  - depth-4 W prefetch ring per row (8 LDG.128 in flight / thread)
// finish: ONE launch, 16384 threads, 16 independent LDG.128 each.

#define BATCH 32
#define DIM   2048
#define NGATE 16
#define KT    16            // split-K factor
#define KC    (DIM / KT)    // 128 k per block
#define KCV   (KC / 4)      // 32 vec4 steps
#define RT    8             // row tiles (256 rows each)
#define BQ    8             // batches per quarter
#define GEMM_BLOCKS (RT * KT * 4)   // 512
#define GATE_BLOCKS 16
#define THREADS 128

__device__ float g_gates[BATCH * NGATE];
__device__ float g_part[KT * BATCH * DIM];   // 4 MB split-K partials

__device__ __forceinline__ void ffma2(unsigned long long& d,
                                      unsigned long long a,
                                      unsigned long long b) {
    asm("fma.rn.f32x2 %0, %1, %2, %0;" : "+l"(d) : "l"(a), "l"(b));
}

__device__ __forceinline__ float2 unpack2(unsigned long long v) {
    float2 r;
    asm("mov.b64 {%0, %1}, %2;" : "=f"(r.x), "=f"(r.y) : "l"(v));
    return r;
}

__global__ __launch_bounds__(THREADS, 4)
void gemm_gate_kernel(const float* __restrict__ x,
                      const float* __restrict__ gate_w,
                      const float* __restrict__ gate_b,
                      const float* __restrict__ weight) {
    __shared__ __align__(16) float smem[BQ * KC];   // 4 KB x quarter-chunk
    const int tid = threadIdx.x;
    const int gb  = blockIdx.x;

    if (gb < GEMM_BLOCKS) {
        // ----- GEMM block: 256 rows x 8 batches x KC k -----
        const int bq = gb & 3;                 // batch quarter (quads adjacent)
        const int kt = (gb >> 2) & (KT - 1);
        const int rt = gb >> 6;
        const int j0 = kt * KC;

        // Stage x quarter-chunk: xs[bb][j], pitch KC. 256 float4 loads.
        {
            const float4* X4  = (const float4*)x;
            float4*       xs4 = (float4*)smem;
#pragma unroll
            for (int idx = tid; idx < BQ * KCV; idx += THREADS) {
                const int bb = idx >> 5;
                const int j4 = idx & 31;
                xs4[idx] = X4[(bq * BQ + bb) * (DIM / 4) + (j0 >> 2) + j4];
            }
        }
        __syncthreads();

        const int i0 = rt * 256 + tid;
        const int i1 = i0 + 128;
        const ulonglong2* __restrict__ Wa =
            (const ulonglong2*)(weight + (size_t)i0 * DIM + j0);
        const ulonglong2* __restrict__ Wb =
            (const ulonglong2*)(weight + (size_t)i1 * DIM + j0);
        const ulonglong2* xs2 = (const ulonglong2*)smem;   // pitch KCV

        unsigned long long accA[BQ], accB[BQ];
#pragma unroll
        for (int b = 0; b < BQ; ++b) { accA[b] = 0ull; accB[b] = 0ull; }

        // Depth-4 prefetch ring per row: 8 LDG.128 in flight / thread.
        ulonglong2 bufA[4], bufB[4];
#pragma unroll
        for (int p = 0; p < 4; ++p) { bufA[p] = Wa[p]; bufB[p] = Wb[p]; }

#pragma unroll 4
        for (int c = 0; c < KCV; ++c) {
            const ulonglong2 wA = bufA[c & 3];
            const ulonglong2 wB = bufB[c & 3];
            const int nj = (c + 4 < KCV) ? (c + 4) : c;   // tail: harmless reload
            bufA[c & 3] = Wa[nj];
            bufB[c & 3] = Wb[nj];
            const ulonglong2* xrow = xs2 + c;
#pragma unroll
            for (int b = 0; b < BQ; ++b) {
                const ulonglong2 xv = xrow[b * KCV];      // uniform -> broadcast
                ffma2(accA[b], wA.x, xv.x);
                ffma2(accA[b], wA.y, xv.y);
                ffma2(accB[b], wB.x, xv.x);
                ffma2(accB[b], wB.y, xv.y);
            }
        }

        float* pA = g_part + (size_t)kt * (BATCH * DIM)
                           + (size_t)(bq * BQ) * DIM + i0;
        float* pB = pA + 128;
#pragma unroll
        for (int b = 0; b < BQ; ++b) {
            const float2 va = unpack2(accA[b]);
            const float2 vb = unpack2(accB[b]);
            pA[b * DIM] = va.x + va.y;    // coalesced 128B across lanes
            pB[b * DIM] = vb.x + vb.y;
        }
    } else {
        // ----- gate block: 2 batch samples -----
        const int b0 = (gb - GEMM_BLOCKS) * 2;
        float* red = smem;            // [128]
        float* sg  = smem + 128;      // [16]
        const int nb = tid >> 3;
        const int pp = tid & 7;

        for (int u = 0; u < 2; ++u) {
            const int b = b0 + u;
            const float* xb = x + b * DIM;
            float a0 = 0.f, a1 = 0.f, a2 = 0.f, a3 = 0.f;
#pragma unroll 4
            for (int j = pp * 4; j < DIM; j += 32) {
                const float4 xv = *(const float4*)(xb + j);
                a0 += xv.x * gate_w[(j + 0) * NGATE + nb];
                a1 += xv.y * gate_w[(j + 1) * NGATE + nb];
                a2 += xv.z * gate_w[(j + 2) * NGATE + nb];
                a3 += xv.w * gate_w[(j + 3) * NGATE + nb];
            }
            red[tid] = (a0 + a1) + (a2 + a3);
            __syncthreads();

            if (tid < NGATE) {
                float s = gate_b[tid];
#pragma unroll
                for (int p = 0; p < 8; ++p) s += red[tid * 8 + p];
                sg[tid] = 1.0f / (1.0f + expf(-s));
            }
            __syncthreads();

            if (tid < NGATE) {
                const float v = sg[tid];
                int rank = 0;   // ascending rank, jax top_k tie-break
#pragma unroll
                for (int j = 0; j < NGATE; ++j) {
                    const float u2 = sg[j];
                    rank += (u2 < v) || (u2 == v && j < tid);
                }
                g_gates[b * NGATE + tid] = (rank >= NGATE / 2) ? v : 0.0f;
            }
            __syncthreads();
        }
    }
}

// Single launch: 16384 threads, one float4 of output each. 16 independent
// LDG.128 in flight per thread; (128,1) lifts the reg-cap heuristic.
__global__ __launch_bounds__(128, 1)
void finish_kernel(const float* __restrict__ bias, float* __restrict__ out) {
    const int t = blockIdx.x * 128 + threadIdx.x;   // float4 unit, 0..16383
    const float4* P4 = (const float4*)g_part;
    float4 p[KT];
#pragma unroll
    for (int kt = 0; kt < KT; ++kt)
        p[kt] = P4[kt * (BATCH * DIM / 4) + t];
    // pairwise tree sum (fixed order: deterministic, high ILP)
#pragma unroll
    for (int s = 1; s < KT; s <<= 1)
#pragma unroll
        for (int k = 0; k < KT; k += 2 * s) {
            p[k].x += p[k + s].x; p[k].y += p[k + s].y;
            p[k].z += p[k + s].z; p[k].w += p[k + s].w;
        }
    const int b  = t >> 9;              // 512 float4 per sample
    const int i4 = t & 511;             // float4 index within row
    const float g  = g_gates[b * NGATE + (i4 >> 5)];   // (i4*4) >> 7
    const float4 bv = ((const float4*)bias)[i4];
    float4 o;
    o.x = g * p[0].x + bv.x;
    o.y = g * p[0].y + bv.y;
    o.z = g * p[0].z + bv.z;
    o.w = g * p[0].w + bv.w;
    ((float4*)out)[t] = o;
}

extern "C" void kernel_launch(void* const* d_in, const int* in_sizes, int n_in,
                              void* d_out, int out_size) {
    const float* x      = (const float*)d_in[0];
    const float* gate_w = (const float*)d_in[1];
    const float* gate_b = (const float*)d_in[2];
    const float* weight = (const float*)d_in[3];
    const float* bias   = (const float*)d_in[4];
    float* out = (float*)d_out;

    gemm_gate_kernel<<<GEMM_BLOCKS + GATE_BLOCKS, THREADS>>>(x, gate_w, gate_b, weight);
    finish_kernel<<<(BATCH * DIM / 4) / 128, 128>>>(bias, out);
}

// round 15
// speedup vs baseline: 1.2301x; 1.2301x over previous
#include <cuda_runtime.h>

// out[b,i] = g[b, i>>7] * (W[i,:] . x[b,:]) + bias[i]
// g = sigmoid(x @ gate_w + gate_b), 8 smallest gates per row zeroed.
//
// R14: W read EXACTLY ONCE (R13 proved GEMM time ~ W DRAM traffic: batch-split
// block replication re-read W from DRAM, no L2 dedup).
//  - 128 GEMM blocks (8 row-tiles x 16 k-tiles) x 256 threads, 1 block/SM
//  - per thread: 1 row x 32 batches (acc = 64 regs), depth-8 W prefetch ring
//  - 16 gate blocks alongside -> 144 blocks, single wave
// finish: 4 threads/output x 4 independent loads + shfl quad-reduce
// (R13 proved 16 loads/thread run as a serial 577cy chain -> 4.8us floor).

#define BATCH 32
#define DIM   2048
#define NGATE 16
#define KT    16            // split-K factor
#define KC    (DIM / KT)    // 128 k per block
#define KCV   (KC / 4)      // 32 vec4 steps
#define RT    8             // row tiles (256 rows each)
#define GEMM_BLOCKS (RT * KT)   // 128
#define GATE_BLOCKS 16
#define THREADS 256

__device__ float g_gates[BATCH * NGATE];
__device__ float g_part[KT * BATCH * DIM];   // 4 MB split-K partials

__device__ __forceinline__ void ffma2(unsigned long long& d,
                                      unsigned long long a,
                                      unsigned long long b) {
    asm("fma.rn.f32x2 %0, %1, %2, %0;" : "+l"(d) : "l"(a), "l"(b));
}

__device__ __forceinline__ float2 unpack2(unsigned long long v) {
    float2 r;
    asm("mov.b64 {%0, %1}, %2;" : "=f"(r.x), "=f"(r.y) : "l"(v));
    return r;
}

__global__ __launch_bounds__(THREADS, 1)
void gemm_gate_kernel(const float* __restrict__ x,
                      const float* __restrict__ gate_w,
                      const float* __restrict__ gate_b,
                      const float* __restrict__ weight) {
    __shared__ __align__(16) float smem[BATCH * KC];   // 16 KB x chunk
    const int tid = threadIdx.x;
    const int gb  = blockIdx.x;

    if (gb < GEMM_BLOCKS) {
        // ----- GEMM block: 256 rows x 32 batches x KC k, W touched once -----
        const int kt = gb & (KT - 1);
        const int rt = gb >> 4;
        const int j0 = kt * KC;

        // Stage x chunk: xs[b][j], pitch KC. 1024 float4 / 256 threads.
        {
            const float4* X4  = (const float4*)x;
            float4*       xs4 = (float4*)smem;
#pragma unroll
            for (int idx = tid; idx < BATCH * KCV; idx += THREADS) {
                const int bb = idx >> 5;
                const int j4 = idx & 31;
                xs4[idx] = X4[bb * (DIM / 4) + (j0 >> 2) + j4];
            }
        }
        __syncthreads();

        const int i = rt * 256 + tid;          // owned output row
        const ulonglong2* __restrict__ W2 =
            (const ulonglong2*)(weight + (size_t)i * DIM + j0);
        const ulonglong2* xs2 = (const ulonglong2*)smem;   // pitch KCV

        unsigned long long acc[BATCH];
#pragma unroll
        for (int b = 0; b < BATCH; ++b) acc[b] = 0ull;

        // Depth-8 prefetch ring: 8 LDG.128 in flight / thread (~1024cy lead).
        ulonglong2 buf[8];
#pragma unroll
        for (int p = 0; p < 8; ++p) buf[p] = W2[p];

#pragma unroll 8
        for (int c = 0; c < KCV; ++c) {
            const ulonglong2 w = buf[c & 7];
            const int nj = (c + 8 < KCV) ? (c + 8) : c;   // tail: harmless reload
            buf[c & 7] = W2[nj];
            const ulonglong2* xrow = xs2 + c;
#pragma unroll
            for (int b = 0; b < BATCH; ++b) {
                const ulonglong2 xv = xrow[b * KCV];      // uniform -> broadcast
                ffma2(acc[b], w.x, xv.x);   // k: 4c .. 4c+1
                ffma2(acc[b], w.y, xv.y);   // k: 4c+2 .. 4c+3
            }
        }

        float* part = g_part + (size_t)kt * (BATCH * DIM) + i;
#pragma unroll
        for (int b = 0; b < BATCH; ++b) {
            const float2 v = unpack2(acc[b]);
            part[b * DIM] = v.x + v.y;       // coalesced across tid
        }
    } else {
        // ----- gate block: 2 batch samples, 256 threads -----
        const int b0 = (gb - GEMM_BLOCKS) * 2;
        float* red = smem;            // [256]
        float* sg  = smem + 256;      // [16]
        const int nb = tid >> 4;      // gate 0..15
        const int pp = tid & 15;      // 16-way k partition

        for (int u = 0; u < 2; ++u) {
            const int b = b0 + u;
            const float* xb = x + b * DIM;
            float a0 = 0.f, a1 = 0.f, a2 = 0.f, a3 = 0.f;
#pragma unroll 4
            for (int j = pp * 4; j < DIM; j += 64) {
                const float4 xv = *(const float4*)(xb + j);
                a0 += xv.x * gate_w[(j + 0) * NGATE + nb];
                a1 += xv.y * gate_w[(j + 1) * NGATE + nb];
                a2 += xv.z * gate_w[(j + 2) * NGATE + nb];
                a3 += xv.w * gate_w[(j + 3) * NGATE + nb];
            }
            red[tid] = (a0 + a1) + (a2 + a3);
            __syncthreads();

            if (tid < NGATE) {
                float s = gate_b[tid];
#pragma unroll
                for (int p = 0; p < 16; ++p) s += red[tid * 16 + p];
                sg[tid] = 1.0f / (1.0f + expf(-s));
            }
            __syncthreads();

            if (tid < NGATE) {
                const float v = sg[tid];
                int rank = 0;   // ascending rank, jax top_k tie-break
#pragma unroll
                for (int j = 0; j < NGATE; ++j) {
                    const float u2 = sg[j];
                    rank += (u2 < v) || (u2 == v && j < tid);
                }
                g_gates[b * NGATE + tid] = (rank >= NGATE / 2) ? v : 0.0f;
            }
            __syncthreads();
        }
    }
}

// 65536 threads: 4 threads per output float4, 4 independent LDG.128 each,
// fixed shfl_xor quad tree (deterministic), lane quad==0 writes.
__global__ __launch_bounds__(128, 1)
void finish_kernel(const float* __restrict__ bias, float* __restrict__ out) {
    const int t    = blockIdx.x * 128 + threadIdx.x;   // 0..65535
    const int o4   = t >> 2;                           // output float4 0..16383
    const int quad = t & 3;                            // slice group
    const float4* P4 = (const float4*)g_part;

    float4 p[4];
#pragma unroll
    for (int s = 0; s < 4; ++s)
        p[s] = P4[(quad * 4 + s) * (BATCH * DIM / 4) + o4];
    float4 a;
    a.x = (p[0].x + p[1].x) + (p[2].x + p[3].x);
    a.y = (p[0].y + p[1].y) + (p[2].y + p[3].y);
    a.z = (p[0].z + p[1].z) + (p[2].z + p[3].z);
    a.w = (p[0].w + p[1].w) + (p[2].w + p[3].w);

    // quad tree: (q0+q1)+(q2+q3), fixed order -> deterministic
#pragma unroll
    for (int m = 1; m <= 2; m <<= 1) {
        a.x += __shfl_xor_sync(0xFFFFFFFFu, a.x, m);
        a.y += __shfl_xor_sync(0xFFFFFFFFu, a.y, m);
        a.z += __shfl_xor_sync(0xFFFFFFFFu, a.z, m);
        a.w += __shfl_xor_sync(0xFFFFFFFFu, a.w, m);
    }

    if (quad == 0) {
        const int b  = o4 >> 9;             // 512 float4 per sample
        const int i4 = o4 & 511;
        const float g  = g_gates[b * NGATE + (i4 >> 5)];   // (i4*4) >> 7
        const float4 bv = ((const float4*)bias)[i4];
        float4 o;
        o.x = g * a.x + bv.x;
        o.y = g * a.y + bv.y;
        o.z = g * a.z + bv.z;
        o.w = g * a.w + bv.w;
        ((float4*)out)[o4] = o;
    }
}

extern "C" void kernel_launch(void* const* d_in, const int* in_sizes, int n_in,
                              void* d_out, int out_size) {
    const float* x      = (const float*)d_in[0];
    const float* gate_w = (const float*)d_in[1];
    const float* gate_b = (const float*)d_in[2];
    const float* weight = (const float*)d_in[3];
    const float* bias   = (const float*)d_in[4];
    float* out = (float*)d_out;

    gemm_gate_kernel<<<GEMM_BLOCKS + GATE_BLOCKS, THREADS>>>(x, gate_w, gate_b, weight);
    finish_kernel<<<(BATCH * DIM) / 128, 128>>>(bias, out);
}